// round 6
// baseline (speedup 1.0000x reference)
#include <cuda_runtime.h>
#include <cuda_bf16.h>
#include <cstdint>
#include <math.h>

#define B_   64
#define C_   192
#define C2_  384
#define HW_  3136            // 56*56
#define M_   (B_*HW_)        // 200704

typedef unsigned long long ull;

// ---------------- scratch (device globals), all channel-major ---------------
__device__ float g_y0    [M_*C_];    // dwconv out  [C][B*HW]
__device__ float g_t1    [M_*C2_];   // lin1 out    [2C][B*HW]  (x | z planes)
__device__ float g_xc    [M_*C_];    // dct1 result [C][B*HW]
__device__ float g_otT   [M_*C_];    // outline transposed [C][B*HW]
__device__ float g_xd    [M_*C2_];   // dct2 result [2C][B*HW]
__device__ float g_y3    [M_*C_];    // lin3 out    [C][B*HW]
__device__ float g_yg    [M_*C_];    // LN*silu     [C][B*HW]
__device__ float g_femixT [HW_*C_];  // [C][HW]
__device__ float g_mult1T [HW_*C_];
__device__ float g_otmeanT[HW_*C_];
__device__ float g_xmeanT [HW_*C2_];
__device__ float g_skftT  [HW_*C2_];
__device__ float g_mult2T [HW_*C2_];
__device__ float g_cos  [HW_];       // cos[n][h]
__device__ float g_cosT [HW_];       // cos[h][n]
__device__ float g_cosP [HW_];       // doubly-permuted (mode-1 B operand)
__device__ float g_dval [HW_];       // wn^2+wm^2 at spatial p=n*56+m

// --------------------------- packed f32x2 helpers ---------------------------
__device__ __forceinline__ ull dup2(float v){
    ull r; asm("mov.b64 %0, {%1, %1};" : "=l"(r) : "f"(v)); return r;
}
__device__ __forceinline__ void fma2(ull &c, ull a, ull b){
    asm("fma.rn.f32x2 %0, %1, %2, %3;" : "=l"(c) : "l"(a), "l"(b), "l"(c));
}
__device__ __forceinline__ ull mul2(ull a, ull b){
    ull r; asm("mul.rn.f32x2 %0, %1, %2;" : "=l"(r) : "l"(a), "l"(b)); return r;
}
__device__ __forceinline__ float2 unpk(ull v){
    float2 f; asm("mov.b64 {%0, %1}, %2;" : "=f"(f.x), "=f"(f.y) : "l"(v)); return f;
}

// ------------------------------- init --------------------------------------
__device__ __forceinline__ float cosv(int n, int h){
    const float PI = 3.14159265358979323846f;
    float v = cosf((float)n * ((h + 0.5f)/56.0f) * PI) * sqrtf(2.0f/56.0f);
    if (n == 0) v *= 0.70710678118654752440f;
    return v;
}
__global__ void init_k(){
    int i = blockIdx.x*blockDim.x + threadIdx.x;
    if (i >= HW_) return;
    int a = i/56, b = i%56;
    g_cos [i] = cosv(a, b);
    g_cosT[i] = cosv(b, a);
    int ja = (a%28)*2 + a/28;     // self-inverse permutation
    int jb = (b%28)*2 + b/28;
    g_cosP[i] = cosv(jb, ja);
    const float PI = 3.14159265358979323846f;
    float wn = PI*(float)a/56.0f, wm = PI*(float)b/56.0f;
    g_dval[i] = wn*wn + wm*wm;
}

// -------------------- depthwise 3x3 conv, plane -> plane -------------------
__global__ __launch_bounds__(256) void dwconv_k(const float* __restrict__ x,
        const float* __restrict__ wc, const float* __restrict__ bc){
    __shared__ float sp[58][58];
    int id = blockIdx.x;
    int c = id % C_, b = id / C_;
    const float* xp = x + ((size_t)b*C_ + c)*HW_;
    int t = threadIdx.x;
    for (int i = t; i < 58*58; i += 256) sp[i/58][i%58] = 0.f;
    __syncthreads();
    for (int i = t; i < HW_; i += 256) sp[i/56 + 1][i%56 + 1] = xp[i];
    float w[9];
    #pragma unroll
    for (int k = 0; k < 9; k++) w[k] = wc[c*9 + k];
    float bias = bc[c];
    __syncthreads();
    float* yp = g_y0 + (size_t)c*M_ + (size_t)b*HW_;
    for (int i = t; i < HW_; i += 256){
        int r = i/56, q = i%56;
        float a = bias;
        #pragma unroll
        for (int dy = 0; dy < 3; dy++)
            #pragma unroll
            for (int dx = 0; dx < 3; dx++)
                a += sp[r+dy][q+dx]*w[dy*3+dx];
        yp[i] = a;
    }
}

// ------------------- transpose outline NHWC -> otT cm ----------------------
__global__ __launch_bounds__(256) void transp_k(const float* __restrict__ in){
    __shared__ float tile[32][33];
    int c0 = blockIdx.x*32;
    int r0 = blockIdx.y*32;
    int lane = threadIdx.x & 31, w = threadIdx.x >> 5;
    #pragma unroll
    for (int i = w; i < 32; i += 8)
        tile[i][lane] = in[(size_t)(r0+i)*C_ + c0 + lane];
    __syncthreads();
    #pragma unroll
    for (int i = w; i < 32; i += 8)
        g_otT[(size_t)(c0+i)*M_ + r0 + lane] = tile[lane][i];
}

// ---------- otmeanT = mean_b(otT); femixT = otmeanT + freq_embed^T ---------
__global__ void otfemix_k(const float* __restrict__ fe){
    int i4 = blockIdx.x*blockDim.x + threadIdx.x;
    if (i4 >= HW_*C_/4) return;
    int c = i4 / (HW_/4), p4 = i4 - c*(HW_/4);
    const float* base = g_otT + (size_t)c*M_ + p4*4;
    float4 s = make_float4(0,0,0,0);
    #pragma unroll 8
    for (int b = 0; b < B_; b++){
        float4 v = *(const float4*)(base + (size_t)b*HW_);
        s.x += v.x; s.y += v.y; s.z += v.z; s.w += v.w;
    }
    const float inv = 1.0f/B_;
    float4 m = make_float4(s.x*inv, s.y*inv, s.z*inv, s.w*inv);
    ((float4*)g_otmeanT)[i4] = m;
    int p = p4*4;
    float4 f = make_float4(fe[(size_t)(p+0)*C_ + c], fe[(size_t)(p+1)*C_ + c],
                           fe[(size_t)(p+2)*C_ + c], fe[(size_t)(p+3)*C_ + c]);
    ((float4*)g_femixT)[i4] = make_float4(m.x+f.x, m.y+f.y, m.z+f.z, m.w+f.w);
}

// ----- xmeanT[c2][p]: c2<C from mean_b(xc); c2>=C copy otmeanT --------------
__global__ void xmean_k(){
    int i4 = blockIdx.x*blockDim.x + threadIdx.x;
    if (i4 >= HW_*C2_/4) return;
    int c2 = i4 / (HW_/4), p4 = i4 - c2*(HW_/4);
    if (c2 < C_){
        const float* base = g_xc + (size_t)c2*M_ + p4*4;
        float4 s = make_float4(0,0,0,0);
        #pragma unroll 8
        for (int b = 0; b < B_; b++){
            float4 v = *(const float4*)(base + (size_t)b*HW_);
            s.x += v.x; s.y += v.y; s.z += v.z; s.w += v.w;
        }
        const float inv = 1.0f/B_;
        ((float4*)g_xmeanT)[i4] = make_float4(s.x*inv, s.y*inv, s.z*inv, s.w*inv);
    } else {
        ((float4*)g_xmeanT)[i4] = ((const float4*)g_otmeanT)[(size_t)(c2-C_)*(HW_/4) + p4];
    }
}

// ---------------- SIMT NN GEMM on channel-major small tensors --------------
template<int EPI>
__global__ __launch_bounds__(256) void cmgemm_k(
        const float* __restrict__ W, const float* __restrict__ X,
        const float* __restrict__ bias, float* __restrict__ Cout,
        int M, int N, int K)
{
    __shared__ float As[16][68];
    __shared__ float Bs[16][68];
    int t = threadIdx.x;
    int m0 = blockIdx.y*64, n0 = blockIdx.x*64;
    int ty = t >> 4, tx = t & 15;
    float acc[4][4];
    #pragma unroll
    for (int i = 0; i < 4; i++){ acc[i][0]=0;acc[i][1]=0;acc[i][2]=0;acc[i][3]=0; }

    int am = t >> 2, akk = (t & 3)*4;
    int bk = t >> 4, bf = (t & 15)*4;

    for (int k0 = 0; k0 < K; k0 += 16){
        float4 wa = *(const float4*)&W[(size_t)(m0+am)*K + k0 + akk];
        float4 xb = *(const float4*)&X[(size_t)(k0+bk)*N + n0 + bf];
        __syncthreads();
        As[akk+0][am] = wa.x; As[akk+1][am] = wa.y;
        As[akk+2][am] = wa.z; As[akk+3][am] = wa.w;
        *(float4*)&Bs[bk][bf] = xb;
        __syncthreads();
        #pragma unroll
        for (int k = 0; k < 16; k++){
            float a[4], b[4];
            #pragma unroll
            for (int i = 0; i < 4; i++) a[i] = As[k][ty*4+i];
            #pragma unroll
            for (int j = 0; j < 4; j++) b[j] = Bs[k][tx*4+j];
            #pragma unroll
            for (int i = 0; i < 4; i++)
                #pragma unroll
                for (int j = 0; j < 4; j++) acc[i][j] += a[i]*b[j];
        }
    }
    #pragma unroll
    for (int i = 0; i < 4; i++){
        int m = m0 + ty*4 + i;
        float bm = bias[m];
        float4 v;
        float* vp = &v.x;
        #pragma unroll
        for (int j = 0; j < 4; j++){
            float u = acc[i][j] + bm;
            if (EPI == 1){
                u = fmaxf(u, 0.f);
                u = expf(-u * g_dval[n0 + tx*4 + j]);
            }
            vp[j] = u;
        }
        *(float4*)&Cout[(size_t)m*N + n0 + tx*4] = v;
    }
}

// ------------------------ tf32 tensor-core NN GEMM -------------------------
__device__ __forceinline__ float to_tf32(float x){
    uint32_t u; asm("cvt.rna.tf32.f32 %0, %1;" : "=r"(u) : "f"(x));
    return __uint_as_float(u);
}
__device__ __forceinline__ void mma_tf32(float c[4], const uint32_t a[4], const uint32_t b[2]){
    asm volatile("mma.sync.aligned.m16n8k8.row.col.f32.tf32.tf32.f32 "
        "{%0,%1,%2,%3}, {%4,%5,%6,%7}, {%8,%9}, {%0,%1,%2,%3};"
        : "+f"(c[0]), "+f"(c[1]), "+f"(c[2]), "+f"(c[3])
        : "r"(a[0]), "r"(a[1]), "r"(a[2]), "r"(a[3]), "r"(b[0]), "r"(b[1]));
}

template<int EPI>
__global__ __launch_bounds__(256) void tgemm_k(
        const float* __restrict__ X, const float* __restrict__ Wm,
        const float* __restrict__ bias, float* __restrict__ Cout,
        int K)
{
    __shared__ float As[2][16][136];
    __shared__ float Bs[2][16][200];
    const int t = threadIdx.x;
    const int lane = t & 31, warp = t >> 5;
    const int gid = lane >> 2, tig = lane & 3;
    const int wm = warp & 3, wn = warp >> 2;
    const int m0 = wm*32, n0 = wn*96;
    const int row0 = blockIdx.y*128, col0 = blockIdx.x*192;

    float acc[2][12][4];
    #pragma unroll
    for (int mt = 0; mt < 2; mt++)
        #pragma unroll
        for (int nt = 0; nt < 12; nt++)
            #pragma unroll
            for (int q = 0; q < 4; q++) acc[mt][nt][q] = 0.f;

    const int af4 = t & 31, ak = t >> 5;
    const float* Ag = X + (size_t)ak*M_ + row0 + af4*4;
    int   brow[3], bk[3];
    const float* Bg[3];
    #pragma unroll
    for (int r = 0; r < 3; r++){
        int idx = t + r*256;
        brow[r] = idx >> 2; bk[r] = (idx & 3)*4;
        Bg[r] = Wm + (size_t)(col0 + brow[r])*K + bk[r];
    }

    float4 pa0, pa1, pb[3];
    pa0 = *(const float4*)(Ag);
    pa1 = *(const float4*)(Ag + (size_t)8*M_);
    #pragma unroll
    for (int r = 0; r < 3; r++) pb[r] = *(const float4*)(Bg[r]);

    {
        float4 q0 = make_float4(to_tf32(pa0.x),to_tf32(pa0.y),to_tf32(pa0.z),to_tf32(pa0.w));
        float4 q1 = make_float4(to_tf32(pa1.x),to_tf32(pa1.y),to_tf32(pa1.z),to_tf32(pa1.w));
        *(float4*)&As[0][ak  ][af4*4] = q0;
        *(float4*)&As[0][ak+8][af4*4] = q1;
        #pragma unroll
        for (int r = 0; r < 3; r++){
            Bs[0][bk[r]+0][brow[r]] = to_tf32(pb[r].x);
            Bs[0][bk[r]+1][brow[r]] = to_tf32(pb[r].y);
            Bs[0][bk[r]+2][brow[r]] = to_tf32(pb[r].z);
            Bs[0][bk[r]+3][brow[r]] = to_tf32(pb[r].w);
        }
    }
    __syncthreads();

    const int nIter = K >> 4;
    int s = 0;
    for (int it = 0; it < nIter; it++){
        if (it + 1 < nIter){
            int k0 = (it+1) << 4;
            pa0 = *(const float4*)(Ag + (size_t)k0*M_);
            pa1 = *(const float4*)(Ag + (size_t)(k0+8)*M_);
            #pragma unroll
            for (int r = 0; r < 3; r++) pb[r] = *(const float4*)(Bg[r] + k0);
        }
        #pragma unroll
        for (int ks = 0; ks < 16; ks += 8){
            uint32_t af[2][4];
            #pragma unroll
            for (int mt = 0; mt < 2; mt++){
                int mm = m0 + mt*16 + gid;
                af[mt][0] = __float_as_uint(As[s][ks+tig  ][mm]);
                af[mt][1] = __float_as_uint(As[s][ks+tig  ][mm+8]);
                af[mt][2] = __float_as_uint(As[s][ks+tig+4][mm]);
                af[mt][3] = __float_as_uint(As[s][ks+tig+4][mm+8]);
            }
            uint32_t bf[12][2];
            #pragma unroll
            for (int nt = 0; nt < 12; nt++){
                int nn = n0 + nt*8 + gid;
                bf[nt][0] = __float_as_uint(Bs[s][ks+tig  ][nn]);
                bf[nt][1] = __float_as_uint(Bs[s][ks+tig+4][nn]);
            }
            #pragma unroll
            for (int mt = 0; mt < 2; mt++)
                #pragma unroll
                for (int nt = 0; nt < 12; nt++)
                    mma_tf32(acc[mt][nt], af[mt], bf[nt]);
        }
        if (it + 1 < nIter){
            int sn = s ^ 1;
            float4 q0 = make_float4(to_tf32(pa0.x),to_tf32(pa0.y),to_tf32(pa0.z),to_tf32(pa0.w));
            float4 q1 = make_float4(to_tf32(pa1.x),to_tf32(pa1.y),to_tf32(pa1.z),to_tf32(pa1.w));
            *(float4*)&As[sn][ak  ][af4*4] = q0;
            *(float4*)&As[sn][ak+8][af4*4] = q1;
            #pragma unroll
            for (int r = 0; r < 3; r++){
                Bs[sn][bk[r]+0][brow[r]] = to_tf32(pb[r].x);
                Bs[sn][bk[r]+1][brow[r]] = to_tf32(pb[r].y);
                Bs[sn][bk[r]+2][brow[r]] = to_tf32(pb[r].z);
                Bs[sn][bk[r]+3][brow[r]] = to_tf32(pb[r].w);
            }
            __syncthreads();
            s = sn;
        }
    }

    #pragma unroll
    for (int mt = 0; mt < 2; mt++){
        #pragma unroll
        for (int nt = 0; nt < 12; nt++){
            int r0 = row0 + m0 + mt*16 + gid;
            int cc = col0 + n0 + nt*8 + tig*2;
            float b0v = bias[cc], b1v = bias[cc+1];
            float v00 = acc[mt][nt][0] + b0v, v01 = acc[mt][nt][1] + b1v;
            float v10 = acc[mt][nt][2] + b0v, v11 = acc[mt][nt][3] + b1v;
            if (EPI == 0){
                Cout[(size_t)cc    *M_ + r0    ] = v00;
                Cout[(size_t)(cc+1)*M_ + r0    ] = v01;
                Cout[(size_t)cc    *M_ + r0 + 8] = v10;
                Cout[(size_t)(cc+1)*M_ + r0 + 8] = v11;
            } else {
                int b0i = r0 / HW_,     p0i = r0 - b0i*HW_;
                int b1i = (r0+8) / HW_, p1i = (r0+8) - b1i*HW_;
                Cout[((size_t)(b0i*C_ + cc  ))*HW_ + p0i] = v00;
                Cout[((size_t)(b0i*C_ + cc+1))*HW_ + p0i] = v01;
                Cout[((size_t)(b1i*C_ + cc  ))*HW_ + p1i] = v10;
                Cout[((size_t)(b1i*C_ + cc+1))*HW_ + p1i] = v11;
            }
        }
    }
}

// ---------------- fused DCT2D * mult * IDCT2D per 56x56 plane --------------
// f32x2-packed 4x4 register tiles (2 col-pairs per thread).
template<int MODE>
__global__ __launch_bounds__(224) void dct_k(const float* __restrict__ inA,
                                             const float* __restrict__ inB,
                                             float* __restrict__ outA,
                                             const float* __restrict__ multT,
                                             const float* __restrict__ cosB)
{
    extern __shared__ float sh[];
    float* Sd = sh;              // [56][56]
    float* Td = sh + 3136;
    float* Cs = sh + 6272;       // cos[n][h]
    float* Cb = sh + 9408;       // B-operand table (cosT or cosP)
    const int t = threadIdx.x;
    const int id = blockIdx.x;

    int b, s = 0, c;
    if (MODE == 0){ b = id / C_; c = id - b*C_; }
    else { b = id / C2_; int rr = id - b*C2_; s = rr / C_; c = rr - s*C_; }

    const float* pinA = inA + (size_t)c*M_ + (size_t)b*HW_;
    const float* pinB = (MODE==1) ? inB + (size_t)c*M_ + (size_t)b*HW_ : nullptr;

    for (int f = t; f < 784; f += 224){
        ((float4*)Cs)[f] = ((const float4*)g_cos)[f];
        ((float4*)Cb)[f] = ((const float4*)cosB)[f];
        if (MODE == 0){
            ((float4*)Sd)[f] = ((const float4*)pinA)[f];
        } else {
            int r = f / 14, g4 = f - r*14;
            int par = g4 / 7, u = (g4 - par*7)*4;
            const float* src = par ? pinB : pinA;
            float4 v = *(const float4*)(src + r*56 + 28*s + u);
            *(float4*)&Sd[r*56 + par*28 + u] = v;
        }
    }
    __syncthreads();

    const bool act = (t < 196);
    int tr = 0, tc = 0;
    if (act){ tr = (t/14)*4; tc = (t - (t/14)*14)*4; }
    ull acc[4][2];

    auto mm56 = [&](const float* Amat, const float* Bmat){
        #pragma unroll
        for (int i = 0; i < 4; i++){ acc[i][0] = 0ULL; acc[i][1] = 0ULL; }
        for (int k4 = 0; k4 < 56; k4 += 4){
            float av[4][4];
            ull   bv[4][2];
            #pragma unroll
            for (int i = 0; i < 4; i++)
                *(float4*)av[i] = *(const float4*)&Amat[(tr+i)*56 + k4];
            #pragma unroll
            for (int kk = 0; kk < 4; kk++){
                ulonglong2 bq = *(const ulonglong2*)&Bmat[(k4+kk)*56 + tc];
                bv[kk][0] = bq.x; bv[kk][1] = bq.y;
            }
            #pragma unroll
            for (int kk = 0; kk < 4; kk++)
                #pragma unroll
                for (int i = 0; i < 4; i++){
                    ull ad = dup2(av[i][kk]);
                    fma2(acc[i][0], ad, bv[kk][0]);
                    fma2(acc[i][1], ad, bv[kk][1]);
                }
        }
    };

    // MM1: Td = Cs x Sd
    if (act){
        mm56(Cs, Sd);
        #pragma unroll
        for (int i = 0; i < 4; i++){
            *(ull*)&Td[(tr+i)*56 + tc]     = acc[i][0];
            *(ull*)&Td[(tr+i)*56 + tc + 2] = acc[i][1];
        }
    }
    __syncthreads();
    // MM2: Sd = (Td x CsB) * mult
    if (act){
        mm56(Td, Cb);
        int par = (MODE==1) ? tc/28 : 0;
        const float* mp = multT + (size_t)(c + C_*par)*HW_;
        int mc = (MODE==1) ? (28*s + (tc - par*28)) : tc;
        #pragma unroll
        for (int i = 0; i < 4; i++){
            ulonglong2 mv = *(const ulonglong2*)&mp[(tr+i)*56 + mc];
            acc[i][0] = mul2(acc[i][0], mv.x);
            acc[i][1] = mul2(acc[i][1], mv.y);
            *(ull*)&Sd[(tr+i)*56 + tc]     = acc[i][0];
            *(ull*)&Sd[(tr+i)*56 + tc + 2] = acc[i][1];
        }
    }
    __syncthreads();
    // MM3: Td = Cs x Sd
    if (act){
        mm56(Cs, Sd);
        #pragma unroll
        for (int i = 0; i < 4; i++){
            *(ull*)&Td[(tr+i)*56 + tc]     = acc[i][0];
            *(ull*)&Td[(tr+i)*56 + tc + 2] = acc[i][1];
        }
    }
    __syncthreads();
    // MM4: out = Td x CsB
    if (act){
        mm56(Td, Cb);
        int par = (MODE==1) ? tc/28 : 0;
        float* op = outA + (size_t)(c + C_*par)*M_ + (size_t)b*HW_;
        int oc = (MODE==1) ? (28*s + (tc - par*28)) : tc;
        #pragma unroll
        for (int i = 0; i < 4; i++){
            float2 lo = unpk(acc[i][0]), hi = unpk(acc[i][1]);
            *(float4*)&op[(tr+i)*56 + oc] = make_float4(lo.x, lo.y, hi.x, hi.y);
        }
    }
}

// ----------------------- LayerNorm(y3) * silu(z), cm -----------------------
__global__ __launch_bounds__(256) void lngate_k(const float* __restrict__ gam,
                                                const float* __restrict__ bet)
{
    __shared__ float sy[C_][33];
    __shared__ float smu[32], srs[32];
    int bp0 = blockIdx.x*32;
    int lane = threadIdx.x & 31, w = threadIdx.x >> 5;
    #pragma unroll
    for (int i = w; i < C_; i += 8)
        sy[i][lane] = g_y3[(size_t)i*M_ + bp0 + lane];
    __syncthreads();
    #pragma unroll
    for (int q = 0; q < 4; q++){
        int p = w*4 + q;
        float sum = 0.f;
        #pragma unroll
        for (int k = 0; k < 6; k++) sum += sy[lane + 32*k][p];
        #pragma unroll
        for (int o = 16; o > 0; o >>= 1) sum += __shfl_xor_sync(0xffffffffu, sum, o);
        float mu = sum * (1.0f/C_);
        float qv = 0.f;
        #pragma unroll
        for (int k = 0; k < 6; k++){ float d = sy[lane + 32*k][p] - mu; qv += d*d; }
        #pragma unroll
        for (int o = 16; o > 0; o >>= 1) qv += __shfl_xor_sync(0xffffffffu, qv, o);
        if (lane == 0){ smu[p] = mu; srs[p] = rsqrtf(qv*(1.0f/C_) + 1e-5f); }
    }
    __syncthreads();
    #pragma unroll
    for (int i = w; i < C_; i += 8){
        float g = gam[i], bb = bet[i];
        float zz = g_t1[(size_t)(C_ + i)*M_ + bp0 + lane];
        float sil = zz / (1.0f + expf(-zz));
        g_yg[(size_t)i*M_ + bp0 + lane] =
            ((sy[i][lane] - smu[lane])*srs[lane]*g + bb) * sil;
    }
}

// --------------------------------- launch ----------------------------------
extern "C" void kernel_launch(void* const* d_in, const int* in_sizes, int n_in,
                              void* d_out, int out_size)
{
    const float* x        = (const float*)d_in[0];
    const float* fe       = (const float*)d_in[1];
    const float* ot       = (const float*)d_in[2];
    const float* dw_w     = (const float*)d_in[3];
    const float* dw_b     = (const float*)d_in[4];
    const float* lin_w    = (const float*)d_in[5];
    const float* lin_b    = (const float*)d_in[6];
    const float* tok_w    = (const float*)d_in[7];
    const float* tok_b    = (const float*)d_in[8];
    const float* lin2_w   = (const float*)d_in[9];
    const float* lin2_b   = (const float*)d_in[10];
    const float* tok2_w   = (const float*)d_in[11];
    const float* tok2_b   = (const float*)d_in[12];
    const float* lin3_w   = (const float*)d_in[13];
    const float* lin3_b   = (const float*)d_in[14];
    const float* norm_g   = (const float*)d_in[15];
    const float* norm_b   = (const float*)d_in[16];
    const float* out_w    = (const float*)d_in[17];
    const float* out_b    = (const float*)d_in[18];
    float* out = (float*)d_out;

    float *y0, *t1, *xc, *otT, *xd, *y3, *yg;
    float *femixT, *mult1T, *xmeanT, *skftT, *mult2T;
    float *cosT, *cosP;
    cudaGetSymbolAddress((void**)&y0,     g_y0);
    cudaGetSymbolAddress((void**)&t1,     g_t1);
    cudaGetSymbolAddress((void**)&xc,     g_xc);
    cudaGetSymbolAddress((void**)&otT,    g_otT);
    cudaGetSymbolAddress((void**)&xd,     g_xd);
    cudaGetSymbolAddress((void**)&y3,     g_y3);
    cudaGetSymbolAddress((void**)&yg,     g_yg);
    cudaGetSymbolAddress((void**)&femixT, g_femixT);
    cudaGetSymbolAddress((void**)&mult1T, g_mult1T);
    cudaGetSymbolAddress((void**)&xmeanT, g_xmeanT);
    cudaGetSymbolAddress((void**)&skftT,  g_skftT);
    cudaGetSymbolAddress((void**)&mult2T, g_mult2T);
    cudaGetSymbolAddress((void**)&cosT,   g_cosT);
    cudaGetSymbolAddress((void**)&cosP,   g_cosP);

    const int DCT_SMEM = 4*3136*4;   // 50176 B
    cudaFuncSetAttribute(dct_k<0>, cudaFuncAttributeMaxDynamicSharedMemorySize, DCT_SMEM);
    cudaFuncSetAttribute(dct_k<1>, cudaFuncAttributeMaxDynamicSharedMemorySize, DCT_SMEM);

    init_k<<<(HW_+255)/256, 256>>>();
    dwconv_k<<<B_*C_, 256>>>(x, dw_w, dw_b);
    transp_k<<<dim3(C_/32, M_/32), 256>>>(ot);
    otfemix_k<<<(HW_*C_/4 + 255)/256, 256>>>(fe);

    cmgemm_k<1><<<dim3(HW_/64, C_/64), 256>>>(tok_w, femixT, tok_b, mult1T,
                                              C_, HW_, C_);
    tgemm_k<0><<<dim3(C2_/192, M_/128), 256>>>(y0, lin_w, lin_b, t1, C_);
    dct_k<0><<<B_*C_, 224, DCT_SMEM>>>(t1, nullptr, xc, mult1T, cosT);

    xmean_k<<<(HW_*C2_/4 + 255)/256, 256>>>();
    cmgemm_k<0><<<dim3(HW_/64, C2_/64), 256>>>(lin2_w, xmeanT, lin2_b, skftT,
                                               C2_, HW_, C2_);
    cmgemm_k<1><<<dim3(HW_/64, C2_/64), 256>>>(tok2_w, skftT, tok2_b, mult2T,
                                               C2_, HW_, C2_);
    dct_k<1><<<B_*C2_, 224, DCT_SMEM>>>(xc, otT, xd, mult2T, cosP);

    tgemm_k<0><<<dim3(1, M_/128), 256>>>(xd, lin3_w, lin3_b, y3, C2_);
    lngate_k<<<M_/32, 256>>>(norm_g, norm_b);
    tgemm_k<1><<<dim3(1, M_/128), 256>>>(yg, out_w, out_b, out, C_);
}

// round 7
// speedup vs baseline: 1.0834x; 1.0834x over previous
#include <cuda_runtime.h>
#include <cuda_bf16.h>
#include <cstdint>
#include <math.h>

#define B_   64
#define C_   192
#define C2_  384
#define HW_  3136            // 56*56
#define M_   (B_*HW_)        // 200704

typedef unsigned long long ull;

// ---------------- scratch (device globals), all channel-major ---------------
__device__ float g_y0    [M_*C_];    // dwconv out  [C][B*HW]
__device__ float g_t1    [M_*C2_];   // lin1 out    [2C][B*HW]  (x | z planes)
__device__ float g_xc    [M_*C_];    // dct1 result [C][B*HW]
__device__ float g_otT   [M_*C_];    // outline transposed [C][B*HW]
__device__ float g_xd    [M_*C2_];   // dct2 result [2C][B*HW]
__device__ float g_y3    [M_*C_];    // lin3 out    [C][B*HW]
__device__ float g_yg    [M_*C_];    // LN*silu     [C][B*HW]
__device__ float g_femixT [HW_*C_];  // [C][HW]
__device__ float g_mult1T [HW_*C_];
__device__ float g_otmeanT[HW_*C_];
__device__ float g_xmeanT [HW_*C2_];
__device__ float g_skftT  [HW_*C2_];
__device__ float g_mult2T [HW_*C2_];
__device__ float g_cos  [HW_];       // cos[n][h]
__device__ float g_cosT [HW_];       // cos[h][n]
__device__ float g_cosP [HW_];       // doubly-permuted (mode-1 B operand)
__device__ float g_dval [HW_];       // wn^2+wm^2 at spatial p=n*56+m

// --------------------------- packed f32x2 helpers ---------------------------
__device__ __forceinline__ ull dup2(float v){
    ull r; asm("mov.b64 %0, {%1, %1};" : "=l"(r) : "f"(v)); return r;
}
__device__ __forceinline__ void fma2(ull &c, ull a, ull b){
    asm("fma.rn.f32x2 %0, %1, %2, %3;" : "=l"(c) : "l"(a), "l"(b), "l"(c));
}
__device__ __forceinline__ ull mul2(ull a, ull b){
    ull r; asm("mul.rn.f32x2 %0, %1, %2;" : "=l"(r) : "l"(a), "l"(b)); return r;
}

// ------------------------------- init --------------------------------------
__device__ __forceinline__ float cosv(int n, int h){
    const float PI = 3.14159265358979323846f;
    float v = cosf((float)n * ((h + 0.5f)/56.0f) * PI) * sqrtf(2.0f/56.0f);
    if (n == 0) v *= 0.70710678118654752440f;
    return v;
}
__global__ void init_k(){
    int i = blockIdx.x*blockDim.x + threadIdx.x;
    if (i >= HW_) return;
    int a = i/56, b = i%56;
    g_cos [i] = cosv(a, b);
    g_cosT[i] = cosv(b, a);
    int ja = (a%28)*2 + a/28;     // self-inverse permutation
    int jb = (b%28)*2 + b/28;
    g_cosP[i] = cosv(jb, ja);
    const float PI = 3.14159265358979323846f;
    float wn = PI*(float)a/56.0f, wm = PI*(float)b/56.0f;
    g_dval[i] = wn*wn + wm*wm;
}

// -------------------- depthwise 3x3 conv, plane -> plane -------------------
__global__ __launch_bounds__(256) void dwconv_k(const float* __restrict__ x,
        const float* __restrict__ wc, const float* __restrict__ bc){
    __shared__ float sp[58][58];
    int id = blockIdx.x;
    int c = id % C_, b = id / C_;
    const float* xp = x + ((size_t)b*C_ + c)*HW_;
    int t = threadIdx.x;
    for (int i = t; i < 58*58; i += 256) sp[i/58][i%58] = 0.f;
    __syncthreads();
    for (int i = t; i < HW_; i += 256) sp[i/56 + 1][i%56 + 1] = xp[i];
    float w[9];
    #pragma unroll
    for (int k = 0; k < 9; k++) w[k] = wc[c*9 + k];
    float bias = bc[c];
    __syncthreads();
    float* yp = g_y0 + (size_t)c*M_ + (size_t)b*HW_;
    for (int i = t; i < HW_; i += 256){
        int r = i/56, q = i%56;
        float a = bias;
        #pragma unroll
        for (int dy = 0; dy < 3; dy++)
            #pragma unroll
            for (int dx = 0; dx < 3; dx++)
                a += sp[r+dy][q+dx]*w[dy*3+dx];
        yp[i] = a;
    }
}

// ------------------- transpose outline NHWC -> otT cm ----------------------
__global__ __launch_bounds__(256) void transp_k(const float* __restrict__ in){
    __shared__ float tile[32][33];
    int c0 = blockIdx.x*32;
    int r0 = blockIdx.y*32;
    int lane = threadIdx.x & 31, w = threadIdx.x >> 5;
    #pragma unroll
    for (int i = w; i < 32; i += 8)
        tile[i][lane] = in[(size_t)(r0+i)*C_ + c0 + lane];
    __syncthreads();
    #pragma unroll
    for (int i = w; i < 32; i += 8)
        g_otT[(size_t)(c0+i)*M_ + r0 + lane] = tile[lane][i];
}

// ---------- otmeanT = mean_b(otT); femixT = otmeanT + freq_embed^T ---------
__global__ void otfemix_k(const float* __restrict__ fe){
    int i4 = blockIdx.x*blockDim.x + threadIdx.x;
    if (i4 >= HW_*C_/4) return;
    int c = i4 / (HW_/4), p4 = i4 - c*(HW_/4);
    const float* base = g_otT + (size_t)c*M_ + p4*4;
    float4 s = make_float4(0,0,0,0);
    #pragma unroll 8
    for (int b = 0; b < B_; b++){
        float4 v = *(const float4*)(base + (size_t)b*HW_);
        s.x += v.x; s.y += v.y; s.z += v.z; s.w += v.w;
    }
    const float inv = 1.0f/B_;
    float4 m = make_float4(s.x*inv, s.y*inv, s.z*inv, s.w*inv);
    ((float4*)g_otmeanT)[i4] = m;
    int p = p4*4;
    float4 f = make_float4(fe[(size_t)(p+0)*C_ + c], fe[(size_t)(p+1)*C_ + c],
                           fe[(size_t)(p+2)*C_ + c], fe[(size_t)(p+3)*C_ + c]);
    ((float4*)g_femixT)[i4] = make_float4(m.x+f.x, m.y+f.y, m.z+f.z, m.w+f.w);
}

// ----- xmeanT[c2][p]: c2<C from mean_b(xc); c2>=C copy otmeanT --------------
__global__ void xmean_k(){
    int i4 = blockIdx.x*blockDim.x + threadIdx.x;
    if (i4 >= HW_*C2_/4) return;
    int c2 = i4 / (HW_/4), p4 = i4 - c2*(HW_/4);
    if (c2 < C_){
        const float* base = g_xc + (size_t)c2*M_ + p4*4;
        float4 s = make_float4(0,0,0,0);
        #pragma unroll 8
        for (int b = 0; b < B_; b++){
            float4 v = *(const float4*)(base + (size_t)b*HW_);
            s.x += v.x; s.y += v.y; s.z += v.z; s.w += v.w;
        }
        const float inv = 1.0f/B_;
        ((float4*)g_xmeanT)[i4] = make_float4(s.x*inv, s.y*inv, s.z*inv, s.w*inv);
    } else {
        ((float4*)g_xmeanT)[i4] = ((const float4*)g_otmeanT)[(size_t)(c2-C_)*(HW_/4) + p4];
    }
}

// ---------------- SIMT NN GEMM on channel-major small tensors --------------
template<int EPI>
__global__ __launch_bounds__(256) void cmgemm_k(
        const float* __restrict__ W, const float* __restrict__ X,
        const float* __restrict__ bias, float* __restrict__ Cout,
        int M, int N, int K)
{
    __shared__ float As[16][68];
    __shared__ float Bs[16][68];
    int t = threadIdx.x;
    int m0 = blockIdx.y*64, n0 = blockIdx.x*64;
    int ty = t >> 4, tx = t & 15;
    float acc[4][4];
    #pragma unroll
    for (int i = 0; i < 4; i++){ acc[i][0]=0;acc[i][1]=0;acc[i][2]=0;acc[i][3]=0; }

    int am = t >> 2, akk = (t & 3)*4;
    int bk = t >> 4, bf = (t & 15)*4;

    for (int k0 = 0; k0 < K; k0 += 16){
        float4 wa = *(const float4*)&W[(size_t)(m0+am)*K + k0 + akk];
        float4 xb = *(const float4*)&X[(size_t)(k0+bk)*N + n0 + bf];
        __syncthreads();
        As[akk+0][am] = wa.x; As[akk+1][am] = wa.y;
        As[akk+2][am] = wa.z; As[akk+3][am] = wa.w;
        *(float4*)&Bs[bk][bf] = xb;
        __syncthreads();
        #pragma unroll
        for (int k = 0; k < 16; k++){
            float a[4], b[4];
            #pragma unroll
            for (int i = 0; i < 4; i++) a[i] = As[k][ty*4+i];
            #pragma unroll
            for (int j = 0; j < 4; j++) b[j] = Bs[k][tx*4+j];
            #pragma unroll
            for (int i = 0; i < 4; i++)
                #pragma unroll
                for (int j = 0; j < 4; j++) acc[i][j] += a[i]*b[j];
        }
    }
    #pragma unroll
    for (int i = 0; i < 4; i++){
        int m = m0 + ty*4 + i;
        float bm = bias[m];
        float4 v;
        float* vp = &v.x;
        #pragma unroll
        for (int j = 0; j < 4; j++){
            float u = acc[i][j] + bm;
            if (EPI == 1){
                u = fmaxf(u, 0.f);
                u = expf(-u * g_dval[n0 + tx*4 + j]);
            }
            vp[j] = u;
        }
        *(float4*)&Cout[(size_t)m*N + n0 + tx*4] = v;
    }
}

// ------------------------ tf32 tensor-core NN GEMM -------------------------
__device__ __forceinline__ float to_tf32(float x){
    uint32_t u; asm("cvt.rna.tf32.f32 %0, %1;" : "=r"(u) : "f"(x));
    return __uint_as_float(u);
}
__device__ __forceinline__ void mma_tf32(float c[4], const uint32_t a[4], const uint32_t b[2]){
    asm volatile("mma.sync.aligned.m16n8k8.row.col.f32.tf32.tf32.f32 "
        "{%0,%1,%2,%3}, {%4,%5,%6,%7}, {%8,%9}, {%0,%1,%2,%3};"
        : "+f"(c[0]), "+f"(c[1]), "+f"(c[2]), "+f"(c[3])
        : "r"(a[0]), "r"(a[1]), "r"(a[2]), "r"(a[3]), "r"(b[0]), "r"(b[1]));
}

template<int EPI>
__global__ __launch_bounds__(256) void tgemm_k(
        const float* __restrict__ X, const float* __restrict__ Wm,
        const float* __restrict__ bias, float* __restrict__ Cout,
        int K)
{
    __shared__ float As[2][16][136];
    __shared__ float Bs[2][16][200];
    const int t = threadIdx.x;
    const int lane = t & 31, warp = t >> 5;
    const int gid = lane >> 2, tig = lane & 3;
    const int wm = warp & 3, wn = warp >> 2;
    const int m0 = wm*32, n0 = wn*96;
    const int row0 = blockIdx.y*128, col0 = blockIdx.x*192;

    float acc[2][12][4];
    #pragma unroll
    for (int mt = 0; mt < 2; mt++)
        #pragma unroll
        for (int nt = 0; nt < 12; nt++)
            #pragma unroll
            for (int q = 0; q < 4; q++) acc[mt][nt][q] = 0.f;

    const int af4 = t & 31, ak = t >> 5;
    const float* Ag = X + (size_t)ak*M_ + row0 + af4*4;
    int   brow[3], bk[3];
    const float* Bg[3];
    #pragma unroll
    for (int r = 0; r < 3; r++){
        int idx = t + r*256;
        brow[r] = idx >> 2; bk[r] = (idx & 3)*4;
        Bg[r] = Wm + (size_t)(col0 + brow[r])*K + bk[r];
    }

    float4 pa0, pa1, pb[3];
    pa0 = *(const float4*)(Ag);
    pa1 = *(const float4*)(Ag + (size_t)8*M_);
    #pragma unroll
    for (int r = 0; r < 3; r++) pb[r] = *(const float4*)(Bg[r]);

    {
        float4 q0 = make_float4(to_tf32(pa0.x),to_tf32(pa0.y),to_tf32(pa0.z),to_tf32(pa0.w));
        float4 q1 = make_float4(to_tf32(pa1.x),to_tf32(pa1.y),to_tf32(pa1.z),to_tf32(pa1.w));
        *(float4*)&As[0][ak  ][af4*4] = q0;
        *(float4*)&As[0][ak+8][af4*4] = q1;
        #pragma unroll
        for (int r = 0; r < 3; r++){
            Bs[0][bk[r]+0][brow[r]] = to_tf32(pb[r].x);
            Bs[0][bk[r]+1][brow[r]] = to_tf32(pb[r].y);
            Bs[0][bk[r]+2][brow[r]] = to_tf32(pb[r].z);
            Bs[0][bk[r]+3][brow[r]] = to_tf32(pb[r].w);
        }
    }
    __syncthreads();

    const int nIter = K >> 4;
    int s = 0;
    for (int it = 0; it < nIter; it++){
        if (it + 1 < nIter){
            int k0 = (it+1) << 4;
            pa0 = *(const float4*)(Ag + (size_t)k0*M_);
            pa1 = *(const float4*)(Ag + (size_t)(k0+8)*M_);
            #pragma unroll
            for (int r = 0; r < 3; r++) pb[r] = *(const float4*)(Bg[r] + k0);
        }
        #pragma unroll
        for (int ks = 0; ks < 16; ks += 8){
            uint32_t af[2][4];
            #pragma unroll
            for (int mt = 0; mt < 2; mt++){
                int mm = m0 + mt*16 + gid;
                af[mt][0] = __float_as_uint(As[s][ks+tig  ][mm]);
                af[mt][1] = __float_as_uint(As[s][ks+tig  ][mm+8]);
                af[mt][2] = __float_as_uint(As[s][ks+tig+4][mm]);
                af[mt][3] = __float_as_uint(As[s][ks+tig+4][mm+8]);
            }
            uint32_t bf[12][2];
            #pragma unroll
            for (int nt = 0; nt < 12; nt++){
                int nn = n0 + nt*8 + gid;
                bf[nt][0] = __float_as_uint(Bs[s][ks+tig  ][nn]);
                bf[nt][1] = __float_as_uint(Bs[s][ks+tig+4][nn]);
            }
            #pragma unroll
            for (int mt = 0; mt < 2; mt++)
                #pragma unroll
                for (int nt = 0; nt < 12; nt++)
                    mma_tf32(acc[mt][nt], af[mt], bf[nt]);
        }
        if (it + 1 < nIter){
            int sn = s ^ 1;
            float4 q0 = make_float4(to_tf32(pa0.x),to_tf32(pa0.y),to_tf32(pa0.z),to_tf32(pa0.w));
            float4 q1 = make_float4(to_tf32(pa1.x),to_tf32(pa1.y),to_tf32(pa1.z),to_tf32(pa1.w));
            *(float4*)&As[sn][ak  ][af4*4] = q0;
            *(float4*)&As[sn][ak+8][af4*4] = q1;
            #pragma unroll
            for (int r = 0; r < 3; r++){
                Bs[sn][bk[r]+0][brow[r]] = to_tf32(pb[r].x);
                Bs[sn][bk[r]+1][brow[r]] = to_tf32(pb[r].y);
                Bs[sn][bk[r]+2][brow[r]] = to_tf32(pb[r].z);
                Bs[sn][bk[r]+3][brow[r]] = to_tf32(pb[r].w);
            }
            __syncthreads();
            s = sn;
        }
    }

    #pragma unroll
    for (int mt = 0; mt < 2; mt++){
        #pragma unroll
        for (int nt = 0; nt < 12; nt++){
            int r0 = row0 + m0 + mt*16 + gid;
            int cc = col0 + n0 + nt*8 + tig*2;
            float b0v = bias[cc], b1v = bias[cc+1];
            float v00 = acc[mt][nt][0] + b0v, v01 = acc[mt][nt][1] + b1v;
            float v10 = acc[mt][nt][2] + b0v, v11 = acc[mt][nt][3] + b1v;
            if (EPI == 0){
                Cout[(size_t)cc    *M_ + r0    ] = v00;
                Cout[(size_t)(cc+1)*M_ + r0    ] = v01;
                Cout[(size_t)cc    *M_ + r0 + 8] = v10;
                Cout[(size_t)(cc+1)*M_ + r0 + 8] = v11;
            } else {
                int b0i = r0 / HW_,     p0i = r0 - b0i*HW_;
                int b1i = (r0+8) / HW_, p1i = (r0+8) - b1i*HW_;
                Cout[((size_t)(b0i*C_ + cc  ))*HW_ + p0i] = v00;
                Cout[((size_t)(b0i*C_ + cc+1))*HW_ + p0i] = v01;
                Cout[((size_t)(b1i*C_ + cc  ))*HW_ + p1i] = v10;
                Cout[((size_t)(b1i*C_ + cc+1))*HW_ + p1i] = v11;
            }
        }
    }
}

// ---------------- fused DCT2D * mult * IDCT2D per 56x56 plane --------------
// One WARP per plane. Thread tile 8 rows x 14 cols (7x4 = 28 active lanes).
// 3 planes per block (96 threads), warp-local sync between stages.
template<int MODE>
__global__ __launch_bounds__(96) void dct_k(const float* __restrict__ inA,
                                            const float* __restrict__ inB,
                                            float* __restrict__ outA,
                                            const float* __restrict__ multT,
                                            const float* __restrict__ cosB)
{
    extern __shared__ float sh[];
    float* Cs = sh;                    // [56][56] cos[n][h]
    float* Cb = sh + 3136;             // B-operand table
    const int tid = threadIdx.x;
    const int wid = tid >> 5, lane = tid & 31;
    float* Sd = sh + 6272 + wid*6272;  // per-warp plane buffers
    float* Td = Sd + 3136;

    // cooperative cos-table load
    for (int f = tid; f < 784; f += 96){
        ((float4*)Cs)[f] = ((const float4*)g_cos)[f];
        ((float4*)Cb)[f] = ((const float4*)cosB)[f];
    }

    const int id = blockIdx.x*3 + wid;
    int b, s = 0, c;
    if (MODE == 0){ b = id / C_; c = id - b*C_; }
    else { b = id / C2_; int rr = id - b*C2_; s = rr / C_; c = rr - s*C_; }

    const float* pinA = inA + (size_t)c*M_ + (size_t)b*HW_;
    const float* pinB = (MODE==1) ? inB + (size_t)c*M_ + (size_t)b*HW_ : nullptr;

    // warp loads its own plane
    for (int f = lane; f < 784; f += 32){
        if (MODE == 0){
            ((float4*)Sd)[f] = ((const float4*)pinA)[f];
        } else {
            int r = f / 14, g4 = f - r*14;
            int par = g4 / 7, u = (g4 - par*7)*4;
            const float* src = par ? pinB : pinA;
            float4 v = *(const float4*)(src + r*56 + 28*s + u);
            *(float4*)&Sd[r*56 + par*28 + u] = v;
        }
    }
    __syncthreads();   // cos tables ready for all warps

    const bool act = (lane < 28);
    const int tr = (lane >> 2) * 8;    // 0..48
    const int tc = (lane & 3) * 14;    // 0,14,28,42
    ull acc[8][7];

    auto mm56 = [&](const float* Amat, const float* Bmat){
        #pragma unroll
        for (int i = 0; i < 8; i++)
            #pragma unroll
            for (int j = 0; j < 7; j++) acc[i][j] = 0ULL;
        for (int k4 = 0; k4 < 56; k4 += 4){
            float4 a4[8];
            #pragma unroll
            for (int i = 0; i < 8; i++)
                a4[i] = *(const float4*)&Amat[(tr+i)*56 + k4];
            #pragma unroll
            for (int kk = 0; kk < 4; kk++){
                ull bv[7];
                #pragma unroll
                for (int j = 0; j < 7; j++)
                    bv[j] = *(const ull*)&Bmat[(k4+kk)*56 + tc + 2*j];
                #pragma unroll
                for (int i = 0; i < 8; i++){
                    float aw = (kk==0) ? a4[i].x : (kk==1) ? a4[i].y
                             : (kk==2) ? a4[i].z : a4[i].w;
                    ull ad = dup2(aw);
                    #pragma unroll
                    for (int j = 0; j < 7; j++) fma2(acc[i][j], ad, bv[j]);
                }
            }
        }
    };

    // MM1: Td = Cs x Sd
    if (act){
        mm56(Cs, Sd);
        #pragma unroll
        for (int i = 0; i < 8; i++)
            #pragma unroll
            for (int j = 0; j < 7; j++)
                *(ull*)&Td[(tr+i)*56 + tc + 2*j] = acc[i][j];
    }
    __syncwarp();
    // MM2: Sd = (Td x Cb) * mult
    if (act){
        mm56(Td, Cb);
        int par = (MODE==1) ? tc/28 : 0;
        const float* mp = multT + (size_t)(c + C_*par)*HW_;
        int mc = (MODE==1) ? (28*s + (tc - par*28)) : tc;
        #pragma unroll
        for (int i = 0; i < 8; i++){
            #pragma unroll
            for (int j = 0; j < 7; j++){
                ull mv = *(const ull*)&mp[(tr+i)*56 + mc + 2*j];
                acc[i][j] = mul2(acc[i][j], mv);
                *(ull*)&Sd[(tr+i)*56 + tc + 2*j] = acc[i][j];
            }
        }
    }
    __syncwarp();
    // MM3: Td = Cs x Sd
    if (act){
        mm56(Cs, Sd);
        #pragma unroll
        for (int i = 0; i < 8; i++)
            #pragma unroll
            for (int j = 0; j < 7; j++)
                *(ull*)&Td[(tr+i)*56 + tc + 2*j] = acc[i][j];
    }
    __syncwarp();
    // MM4: out = Td x Cb
    if (act){
        mm56(Td, Cb);
        int par = (MODE==1) ? tc/28 : 0;
        float* op = outA + (size_t)(c + C_*par)*M_ + (size_t)b*HW_;
        int oc = (MODE==1) ? (28*s + (tc - par*28)) : tc;
        #pragma unroll
        for (int i = 0; i < 8; i++)
            #pragma unroll
            for (int j = 0; j < 7; j++)
                *(ull*)&op[(tr+i)*56 + oc + 2*j] = acc[i][j];
    }
}

// ----------------------- LayerNorm(y3) * silu(z), cm -----------------------
__global__ __launch_bounds__(256) void lngate_k(const float* __restrict__ gam,
                                                const float* __restrict__ bet)
{
    __shared__ float sy[C_][33];
    __shared__ float smu[32], srs[32];
    int bp0 = blockIdx.x*32;
    int lane = threadIdx.x & 31, w = threadIdx.x >> 5;
    #pragma unroll
    for (int i = w; i < C_; i += 8)
        sy[i][lane] = g_y3[(size_t)i*M_ + bp0 + lane];
    __syncthreads();
    #pragma unroll
    for (int q = 0; q < 4; q++){
        int p = w*4 + q;
        float sum = 0.f;
        #pragma unroll
        for (int k = 0; k < 6; k++) sum += sy[lane + 32*k][p];
        #pragma unroll
        for (int o = 16; o > 0; o >>= 1) sum += __shfl_xor_sync(0xffffffffu, sum, o);
        float mu = sum * (1.0f/C_);
        float qv = 0.f;
        #pragma unroll
        for (int k = 0; k < 6; k++){ float d = sy[lane + 32*k][p] - mu; qv += d*d; }
        #pragma unroll
        for (int o = 16; o > 0; o >>= 1) qv += __shfl_xor_sync(0xffffffffu, qv, o);
        if (lane == 0){ smu[p] = mu; srs[p] = rsqrtf(qv*(1.0f/C_) + 1e-5f); }
    }
    __syncthreads();
    #pragma unroll
    for (int i = w; i < C_; i += 8){
        float g = gam[i], bb = bet[i];
        float zz = g_t1[(size_t)(C_ + i)*M_ + bp0 + lane];
        float sil = zz / (1.0f + expf(-zz));
        g_yg[(size_t)i*M_ + bp0 + lane] =
            ((sy[i][lane] - smu[lane])*srs[lane]*g + bb) * sil;
    }
}

// --------------------------------- launch ----------------------------------
extern "C" void kernel_launch(void* const* d_in, const int* in_sizes, int n_in,
                              void* d_out, int out_size)
{
    const float* x        = (const float*)d_in[0];
    const float* fe       = (const float*)d_in[1];
    const float* ot       = (const float*)d_in[2];
    const float* dw_w     = (const float*)d_in[3];
    const float* dw_b     = (const float*)d_in[4];
    const float* lin_w    = (const float*)d_in[5];
    const float* lin_b    = (const float*)d_in[6];
    const float* tok_w    = (const float*)d_in[7];
    const float* tok_b    = (const float*)d_in[8];
    const float* lin2_w   = (const float*)d_in[9];
    const float* lin2_b   = (const float*)d_in[10];
    const float* tok2_w   = (const float*)d_in[11];
    const float* tok2_b   = (const float*)d_in[12];
    const float* lin3_w   = (const float*)d_in[13];
    const float* lin3_b   = (const float*)d_in[14];
    const float* norm_g   = (const float*)d_in[15];
    const float* norm_b   = (const float*)d_in[16];
    const float* out_w    = (const float*)d_in[17];
    const float* out_b    = (const float*)d_in[18];
    float* out = (float*)d_out;

    float *y0, *t1, *xc, *otT, *xd, *y3, *yg;
    float *femixT, *mult1T, *xmeanT, *skftT, *mult2T;
    float *cosT, *cosP;
    cudaGetSymbolAddress((void**)&y0,     g_y0);
    cudaGetSymbolAddress((void**)&t1,     g_t1);
    cudaGetSymbolAddress((void**)&xc,     g_xc);
    cudaGetSymbolAddress((void**)&otT,    g_otT);
    cudaGetSymbolAddress((void**)&xd,     g_xd);
    cudaGetSymbolAddress((void**)&y3,     g_y3);
    cudaGetSymbolAddress((void**)&yg,     g_yg);
    cudaGetSymbolAddress((void**)&femixT, g_femixT);
    cudaGetSymbolAddress((void**)&mult1T, g_mult1T);
    cudaGetSymbolAddress((void**)&xmeanT, g_xmeanT);
    cudaGetSymbolAddress((void**)&skftT,  g_skftT);
    cudaGetSymbolAddress((void**)&mult2T, g_mult2T);
    cudaGetSymbolAddress((void**)&cosT,   g_cosT);
    cudaGetSymbolAddress((void**)&cosP,   g_cosP);

    const int DCT_SMEM = 8*3136*4;   // 100352 B: 2 cos tables + 3x(Sd,Td)
    cudaFuncSetAttribute(dct_k<0>, cudaFuncAttributeMaxDynamicSharedMemorySize, DCT_SMEM);
    cudaFuncSetAttribute(dct_k<1>, cudaFuncAttributeMaxDynamicSharedMemorySize, DCT_SMEM);

    init_k<<<(HW_+255)/256, 256>>>();
    dwconv_k<<<B_*C_, 256>>>(x, dw_w, dw_b);
    transp_k<<<dim3(C_/32, M_/32), 256>>>(ot);
    otfemix_k<<<(HW_*C_/4 + 255)/256, 256>>>(fe);

    cmgemm_k<1><<<dim3(HW_/64, C_/64), 256>>>(tok_w, femixT, tok_b, mult1T,
                                              C_, HW_, C_);
    tgemm_k<0><<<dim3(C2_/192, M_/128), 256>>>(y0, lin_w, lin_b, t1, C_);
    dct_k<0><<<B_*C_/3, 96, DCT_SMEM>>>(t1, nullptr, xc, mult1T, cosT);

    xmean_k<<<(HW_*C2_/4 + 255)/256, 256>>>();
    cmgemm_k<0><<<dim3(HW_/64, C2_/64), 256>>>(lin2_w, xmeanT, lin2_b, skftT,
                                               C2_, HW_, C2_);
    cmgemm_k<1><<<dim3(HW_/64, C2_/64), 256>>>(tok2_w, skftT, tok2_b, mult2T,
                                               C2_, HW_, C2_);
    dct_k<1><<<B_*C2_/3, 96, DCT_SMEM>>>(xc, otT, xd, mult2T, cosP);

    tgemm_k<0><<<dim3(1, M_/128), 256>>>(xd, lin3_w, lin3_b, y3, C2_);
    lngate_k<<<M_/32, 256>>>(norm_g, norm_b);
    tgemm_k<1><<<dim3(1, M_/128), 256>>>(yg, out_w, out_b, out, C_);
}

// round 8
// speedup vs baseline: 1.1883x; 1.0969x over previous
#include <cuda_runtime.h>
#include <cuda_bf16.h>
#include <cstdint>
#include <math.h>

#define B_   64
#define C_   192
#define C2_  384
#define HW_  3136            // 56*56
#define M_   (B_*HW_)        // 200704
#define PST  58              // padded row stride for plane smem buffers

typedef unsigned long long ull;

// ---------------- scratch (device globals), all channel-major ---------------
__device__ float g_y0    [M_*C_];    // dwconv out  [C][B*HW]
__device__ float g_t1    [M_*C2_];   // lin1 out    [2C][B*HW]  (x | z planes)
__device__ float g_xc    [M_*C_];    // dct1 result [C][B*HW]
__device__ float g_otT   [M_*C_];    // outline transposed [C][B*HW]
__device__ float g_xd    [M_*C2_];   // dct2 result [2C][B*HW]
__device__ float g_y3    [M_*C_];    // lin3 out    [C][B*HW]
__device__ float g_yg    [M_*C_];    // LN*silu     [C][B*HW]
__device__ float g_femixT [HW_*C_];  // [C][HW]
__device__ float g_mult1T [HW_*C_];
__device__ float g_otmeanT[HW_*C_];
__device__ float g_xmeanT [HW_*C2_];
__device__ float g_skftT  [HW_*C2_];
__device__ float g_mult2T [HW_*C2_];
__device__ float g_cos  [HW_];       // cos[n][h]
__device__ float g_cosT [HW_];       // cos[h][n]
__device__ float g_cosP [HW_];       // doubly-permuted (mode-1 B operand)
__device__ float g_dval [HW_];       // wn^2+wm^2 at spatial p=n*56+m

// --------------------------- packed f32x2 helpers ---------------------------
__device__ __forceinline__ ull dup2(float v){
    ull r; asm("mov.b64 %0, {%1, %1};" : "=l"(r) : "f"(v)); return r;
}
__device__ __forceinline__ void fma2(ull &c, ull a, ull b){
    asm("fma.rn.f32x2 %0, %1, %2, %3;" : "=l"(c) : "l"(a), "l"(b), "l"(c));
}
__device__ __forceinline__ ull mul2(ull a, ull b){
    ull r; asm("mul.rn.f32x2 %0, %1, %2;" : "=l"(r) : "l"(a), "l"(b)); return r;
}

// ------------------------------- init --------------------------------------
__device__ __forceinline__ float cosv(int n, int h){
    const float PI = 3.14159265358979323846f;
    float v = cosf((float)n * ((h + 0.5f)/56.0f) * PI) * sqrtf(2.0f/56.0f);
    if (n == 0) v *= 0.70710678118654752440f;
    return v;
}
__global__ void init_k(){
    int i = blockIdx.x*blockDim.x + threadIdx.x;
    if (i >= HW_) return;
    int a = i/56, b = i%56;
    g_cos [i] = cosv(a, b);
    g_cosT[i] = cosv(b, a);
    int ja = (a%28)*2 + a/28;
    int jb = (b%28)*2 + b/28;
    g_cosP[i] = cosv(jb, ja);
    const float PI = 3.14159265358979323846f;
    float wn = PI*(float)a/56.0f, wm = PI*(float)b/56.0f;
    g_dval[i] = wn*wn + wm*wm;
}

// -------------------- depthwise 3x3 conv, plane -> plane -------------------
__global__ __launch_bounds__(256) void dwconv_k(const float* __restrict__ x,
        const float* __restrict__ wc, const float* __restrict__ bc){
    __shared__ float sp[58][58];
    int id = blockIdx.x;
    int c = id % C_, b = id / C_;
    const float* xp = x + ((size_t)b*C_ + c)*HW_;
    int t = threadIdx.x;
    for (int i = t; i < 58*58; i += 256) sp[i/58][i%58] = 0.f;
    __syncthreads();
    for (int i = t; i < HW_; i += 256) sp[i/56 + 1][i%56 + 1] = xp[i];
    float w[9];
    #pragma unroll
    for (int k = 0; k < 9; k++) w[k] = wc[c*9 + k];
    float bias = bc[c];
    __syncthreads();
    float* yp = g_y0 + (size_t)c*M_ + (size_t)b*HW_;
    for (int i = t; i < HW_; i += 256){
        int r = i/56, q = i%56;
        float a = bias;
        #pragma unroll
        for (int dy = 0; dy < 3; dy++)
            #pragma unroll
            for (int dx = 0; dx < 3; dx++)
                a += sp[r+dy][q+dx]*w[dy*3+dx];
        yp[i] = a;
    }
}

// ------------------- transpose outline NHWC -> otT cm ----------------------
__global__ __launch_bounds__(256) void transp_k(const float* __restrict__ in){
    __shared__ float tile[32][33];
    int c0 = blockIdx.x*32;
    int r0 = blockIdx.y*32;
    int lane = threadIdx.x & 31, w = threadIdx.x >> 5;
    #pragma unroll
    for (int i = w; i < 32; i += 8)
        tile[i][lane] = in[(size_t)(r0+i)*C_ + c0 + lane];
    __syncthreads();
    #pragma unroll
    for (int i = w; i < 32; i += 8)
        g_otT[(size_t)(c0+i)*M_ + r0 + lane] = tile[lane][i];
}

// ---------- otmeanT = mean_b(otT); femixT = otmeanT + freq_embed^T ---------
__global__ void otfemix_k(const float* __restrict__ fe){
    int i4 = blockIdx.x*blockDim.x + threadIdx.x;
    if (i4 >= HW_*C_/4) return;
    int c = i4 / (HW_/4), p4 = i4 - c*(HW_/4);
    const float* base = g_otT + (size_t)c*M_ + p4*4;
    float4 s = make_float4(0,0,0,0);
    #pragma unroll 8
    for (int b = 0; b < B_; b++){
        float4 v = *(const float4*)(base + (size_t)b*HW_);
        s.x += v.x; s.y += v.y; s.z += v.z; s.w += v.w;
    }
    const float inv = 1.0f/B_;
    float4 m = make_float4(s.x*inv, s.y*inv, s.z*inv, s.w*inv);
    ((float4*)g_otmeanT)[i4] = m;
    int p = p4*4;
    float4 f = make_float4(fe[(size_t)(p+0)*C_ + c], fe[(size_t)(p+1)*C_ + c],
                           fe[(size_t)(p+2)*C_ + c], fe[(size_t)(p+3)*C_ + c]);
    ((float4*)g_femixT)[i4] = make_float4(m.x+f.x, m.y+f.y, m.z+f.z, m.w+f.w);
}

// ----- xmeanT[c2][p]: c2<C from mean_b(xc); c2>=C copy otmeanT --------------
__global__ void xmean_k(){
    int i4 = blockIdx.x*blockDim.x + threadIdx.x;
    if (i4 >= HW_*C2_/4) return;
    int c2 = i4 / (HW_/4), p4 = i4 - c2*(HW_/4);
    if (c2 < C_){
        const float* base = g_xc + (size_t)c2*M_ + p4*4;
        float4 s = make_float4(0,0,0,0);
        #pragma unroll 8
        for (int b = 0; b < B_; b++){
            float4 v = *(const float4*)(base + (size_t)b*HW_);
            s.x += v.x; s.y += v.y; s.z += v.z; s.w += v.w;
        }
        const float inv = 1.0f/B_;
        ((float4*)g_xmeanT)[i4] = make_float4(s.x*inv, s.y*inv, s.z*inv, s.w*inv);
    } else {
        ((float4*)g_xmeanT)[i4] = ((const float4*)g_otmeanT)[(size_t)(c2-C_)*(HW_/4) + p4];
    }
}

// ---------------- SIMT NN GEMM on channel-major small tensors --------------
template<int EPI>
__global__ __launch_bounds__(256) void cmgemm_k(
        const float* __restrict__ W, const float* __restrict__ X,
        const float* __restrict__ bias, float* __restrict__ Cout,
        int M, int N, int K)
{
    __shared__ float As[16][68];
    __shared__ float Bs[16][68];
    int t = threadIdx.x;
    int m0 = blockIdx.y*64, n0 = blockIdx.x*64;
    int ty = t >> 4, tx = t & 15;
    float acc[4][4];
    #pragma unroll
    for (int i = 0; i < 4; i++){ acc[i][0]=0;acc[i][1]=0;acc[i][2]=0;acc[i][3]=0; }

    int am = t >> 2, akk = (t & 3)*4;
    int bk = t >> 4, bf = (t & 15)*4;

    for (int k0 = 0; k0 < K; k0 += 16){
        float4 wa = *(const float4*)&W[(size_t)(m0+am)*K + k0 + akk];
        float4 xb = *(const float4*)&X[(size_t)(k0+bk)*N + n0 + bf];
        __syncthreads();
        As[akk+0][am] = wa.x; As[akk+1][am] = wa.y;
        As[akk+2][am] = wa.z; As[akk+3][am] = wa.w;
        *(float4*)&Bs[bk][bf] = xb;
        __syncthreads();
        #pragma unroll
        for (int k = 0; k < 16; k++){
            float a[4], b[4];
            #pragma unroll
            for (int i = 0; i < 4; i++) a[i] = As[k][ty*4+i];
            #pragma unroll
            for (int j = 0; j < 4; j++) b[j] = Bs[k][tx*4+j];
            #pragma unroll
            for (int i = 0; i < 4; i++)
                #pragma unroll
                for (int j = 0; j < 4; j++) acc[i][j] += a[i]*b[j];
        }
    }
    #pragma unroll
    for (int i = 0; i < 4; i++){
        int m = m0 + ty*4 + i;
        float bm = bias[m];
        float4 v;
        float* vp = &v.x;
        #pragma unroll
        for (int j = 0; j < 4; j++){
            float u = acc[i][j] + bm;
            if (EPI == 1){
                u = fmaxf(u, 0.f);
                u = expf(-u * g_dval[n0 + tx*4 + j]);
            }
            vp[j] = u;
        }
        *(float4*)&Cout[(size_t)m*N + n0 + tx*4] = v;
    }
}

// ------------------------ tf32 tensor-core NN GEMM -------------------------
__device__ __forceinline__ float to_tf32(float x){
    uint32_t u; asm("cvt.rna.tf32.f32 %0, %1;" : "=r"(u) : "f"(x));
    return __uint_as_float(u);
}
__device__ __forceinline__ void mma_tf32(float c[4], const uint32_t a[4], const uint32_t b[2]){
    asm volatile("mma.sync.aligned.m16n8k8.row.col.f32.tf32.tf32.f32 "
        "{%0,%1,%2,%3}, {%4,%5,%6,%7}, {%8,%9}, {%0,%1,%2,%3};"
        : "+f"(c[0]), "+f"(c[1]), "+f"(c[2]), "+f"(c[3])
        : "r"(a[0]), "r"(a[1]), "r"(a[2]), "r"(a[3]), "r"(b[0]), "r"(b[1]));
}

template<int EPI>
__global__ __launch_bounds__(256) void tgemm_k(
        const float* __restrict__ X, const float* __restrict__ Wm,
        const float* __restrict__ bias, float* __restrict__ Cout,
        int K)
{
    __shared__ float As[2][16][136];
    __shared__ float Bs[2][16][200];
    const int t = threadIdx.x;
    const int lane = t & 31, warp = t >> 5;
    const int gid = lane >> 2, tig = lane & 3;
    const int wm = warp & 3, wn = warp >> 2;
    const int m0 = wm*32, n0 = wn*96;
    const int row0 = blockIdx.y*128, col0 = blockIdx.x*192;

    float acc[2][12][4];
    #pragma unroll
    for (int mt = 0; mt < 2; mt++)
        #pragma unroll
        for (int nt = 0; nt < 12; nt++)
            #pragma unroll
            for (int q = 0; q < 4; q++) acc[mt][nt][q] = 0.f;

    const int af4 = t & 31, ak = t >> 5;
    const float* Ag = X + (size_t)ak*M_ + row0 + af4*4;
    int   brow[3], bk[3];
    const float* Bg[3];
    #pragma unroll
    for (int r = 0; r < 3; r++){
        int idx = t + r*256;
        brow[r] = idx >> 2; bk[r] = (idx & 3)*4;
        Bg[r] = Wm + (size_t)(col0 + brow[r])*K + bk[r];
    }

    float4 pa0, pa1, pb[3];
    pa0 = *(const float4*)(Ag);
    pa1 = *(const float4*)(Ag + (size_t)8*M_);
    #pragma unroll
    for (int r = 0; r < 3; r++) pb[r] = *(const float4*)(Bg[r]);

    {
        float4 q0 = make_float4(to_tf32(pa0.x),to_tf32(pa0.y),to_tf32(pa0.z),to_tf32(pa0.w));
        float4 q1 = make_float4(to_tf32(pa1.x),to_tf32(pa1.y),to_tf32(pa1.z),to_tf32(pa1.w));
        *(float4*)&As[0][ak  ][af4*4] = q0;
        *(float4*)&As[0][ak+8][af4*4] = q1;
        #pragma unroll
        for (int r = 0; r < 3; r++){
            Bs[0][bk[r]+0][brow[r]] = to_tf32(pb[r].x);
            Bs[0][bk[r]+1][brow[r]] = to_tf32(pb[r].y);
            Bs[0][bk[r]+2][brow[r]] = to_tf32(pb[r].z);
            Bs[0][bk[r]+3][brow[r]] = to_tf32(pb[r].w);
        }
    }
    __syncthreads();

    const int nIter = K >> 4;
    int s = 0;
    for (int it = 0; it < nIter; it++){
        if (it + 1 < nIter){
            int k0 = (it+1) << 4;
            pa0 = *(const float4*)(Ag + (size_t)k0*M_);
            pa1 = *(const float4*)(Ag + (size_t)(k0+8)*M_);
            #pragma unroll
            for (int r = 0; r < 3; r++) pb[r] = *(const float4*)(Bg[r] + k0);
        }
        #pragma unroll
        for (int ks = 0; ks < 16; ks += 8){
            uint32_t af[2][4];
            #pragma unroll
            for (int mt = 0; mt < 2; mt++){
                int mm = m0 + mt*16 + gid;
                af[mt][0] = __float_as_uint(As[s][ks+tig  ][mm]);
                af[mt][1] = __float_as_uint(As[s][ks+tig  ][mm+8]);
                af[mt][2] = __float_as_uint(As[s][ks+tig+4][mm]);
                af[mt][3] = __float_as_uint(As[s][ks+tig+4][mm+8]);
            }
            uint32_t bf[12][2];
            #pragma unroll
            for (int nt = 0; nt < 12; nt++){
                int nn = n0 + nt*8 + gid;
                bf[nt][0] = __float_as_uint(Bs[s][ks+tig  ][nn]);
                bf[nt][1] = __float_as_uint(Bs[s][ks+tig+4][nn]);
            }
            #pragma unroll
            for (int mt = 0; mt < 2; mt++)
                #pragma unroll
                for (int nt = 0; nt < 12; nt++)
                    mma_tf32(acc[mt][nt], af[mt], bf[nt]);
        }
        if (it + 1 < nIter){
            int sn = s ^ 1;
            float4 q0 = make_float4(to_tf32(pa0.x),to_tf32(pa0.y),to_tf32(pa0.z),to_tf32(pa0.w));
            float4 q1 = make_float4(to_tf32(pa1.x),to_tf32(pa1.y),to_tf32(pa1.z),to_tf32(pa1.w));
            *(float4*)&As[sn][ak  ][af4*4] = q0;
            *(float4*)&As[sn][ak+8][af4*4] = q1;
            #pragma unroll
            for (int r = 0; r < 3; r++){
                Bs[sn][bk[r]+0][brow[r]] = to_tf32(pb[r].x);
                Bs[sn][bk[r]+1][brow[r]] = to_tf32(pb[r].y);
                Bs[sn][bk[r]+2][brow[r]] = to_tf32(pb[r].z);
                Bs[sn][bk[r]+3][brow[r]] = to_tf32(pb[r].w);
            }
            __syncthreads();
            s = sn;
        }
    }

    #pragma unroll
    for (int mt = 0; mt < 2; mt++){
        #pragma unroll
        for (int nt = 0; nt < 12; nt++){
            int r0 = row0 + m0 + mt*16 + gid;
            int cc = col0 + n0 + nt*8 + tig*2;
            float b0v = bias[cc], b1v = bias[cc+1];
            float v00 = acc[mt][nt][0] + b0v, v01 = acc[mt][nt][1] + b1v;
            float v10 = acc[mt][nt][2] + b0v, v11 = acc[mt][nt][3] + b1v;
            if (EPI == 0){
                Cout[(size_t)cc    *M_ + r0    ] = v00;
                Cout[(size_t)(cc+1)*M_ + r0    ] = v01;
                Cout[(size_t)cc    *M_ + r0 + 8] = v10;
                Cout[(size_t)(cc+1)*M_ + r0 + 8] = v11;
            } else {
                int b0i = r0 / HW_,     p0i = r0 - b0i*HW_;
                int b1i = (r0+8) / HW_, p1i = (r0+8) - b1i*HW_;
                Cout[((size_t)(b0i*C_ + cc  ))*HW_ + p0i] = v00;
                Cout[((size_t)(b0i*C_ + cc+1))*HW_ + p0i] = v01;
                Cout[((size_t)(b1i*C_ + cc  ))*HW_ + p1i] = v10;
                Cout[((size_t)(b1i*C_ + cc+1))*HW_ + p1i] = v11;
            }
        }
    }
}

// ---------------- fused DCT2D * mult * IDCT2D per 56x56 plane --------------
// Folded transforms (mirror symmetry of the cos basis): every matmul has K=28.
// 2 warps per plane (even/odd output rows), 2 planes per block (128 threads).
// MM1/MM3: out[n] = sum_{h<28} Cs[n][h] * (Sd[h] +/- Sd[55-h]);  +/- by n parity.
// MM2/MM4: fold over contraction cols; MODE 0 sign alternates per output col
//          -> interleaved {E,O} pairs feed fma.f32x2 directly; MODE 1 sign is
//          by column block (m<28 vs m>=28) -> blocked E|O with dup2.
template<int MODE>
__global__ __launch_bounds__(128) void dct_k(const float* __restrict__ inA,
                                             const float* __restrict__ inB,
                                             float* __restrict__ outA,
                                             const float* __restrict__ multT,
                                             const float* __restrict__ cosB)
{
    extern __shared__ float sh[];
    float* CsH = sh;                     // [56][28] stride 29
    float* CbF = sh + 56*29;             // [28][56] stride 58
    const int tid  = threadIdx.x;
    const int wid  = tid >> 5, lane = tid & 31;
    const int pl   = wid >> 1;           // plane within block (0/1)
    const int p    = wid & 1;            // row parity handled by this warp
    float* P0 = sh + 56*29 + 28*58 + pl*(2*56*PST);
    float* P1 = P0 + 56*PST;

    // ---- tables (block-cooperative) ----
    for (int idx = tid; idx < 56*28; idx += 128){
        int n = idx/28, k = idx - n*28;
        CsH[n*29 + k] = g_cos[n*56 + k];
    }
    for (int idx = tid; idx < 28*56; idx += 128){
        int k = idx/56, m = idx - k*56;
        CbF[k*58 + m] = cosB[k*56 + m];
    }

    // ---- plane id / pointers ----
    const int id = blockIdx.x*2 + pl;
    int b, s = 0, c;
    if (MODE == 0){ b = id / C_; c = id - b*C_; }
    else { b = id / C2_; int rr = id - b*C2_; s = rr / C_; c = rr - s*C_; }
    const float* pinA = inA + (size_t)c*M_ + (size_t)b*HW_;
    const float* pinB = (MODE==1) ? inB + (size_t)c*M_ + (size_t)b*HW_ : nullptr;

    // ---- load plane into P0 (both warps of the plane cooperate) ----
    {
        int tl = tid & 63;
        for (int f = tl; f < 1568; f += 64){
            int r = f/28, q = f - r*28;
            if (MODE == 0){
                *(ull*)&P0[r*PST + 2*q] = *(const ull*)(pinA + r*56 + 2*q);
            } else {
                int par = q/14, u = (q - par*14)*2;
                const float* src = par ? pinB : pinA;
                *(ull*)&P0[r*PST + par*28 + u] = *(const ull*)(src + r*56 + 28*s + u);
            }
        }
    }
    __syncthreads();

    const bool act = (lane < 28);
    const int ri = lane >> 2;            // 0..6 (row group)
    const int tc = (lane & 3)*14;        // 0,14,28,42 (col group)
    const int coff = (MODE==1 && tc >= 28) ? 28 : 0;  // E/O block select (mode 1)
    ull acc[4][7];
    ull bvec[7];

    // row-mirror fold P0 -> P1 halves (E rows 0..27 if p==0, O rows 28..55 if p==1)
    auto rowfold = [&](){
        for (int idx = lane; idx < 1568; idx += 32){
            int hh = idx/56, w = idx - hh*56;
            float a = P0[hh*PST + w], bb = P0[(55-hh)*PST + w];
            P1[(28*p + hh)*PST + w] = p ? (a - bb) : (a + bb);
        }
    };
    // column-mirror fold (row-local, this warp's parity rows) P0 -> P1 slots
    auto colfold = [&](){
        for (int idx = lane; idx < 784; idx += 32){
            int nn = idx/28, wt = idx - nn*28;
            int n = 2*nn + p;
            float a = P0[n*PST + wt], bb = P0[n*PST + 55 - wt];
            if (MODE == 0){
                P1[(28*p + nn)*PST + 2*wt]     = a + bb;
                P1[(28*p + nn)*PST + 2*wt + 1] = a - bb;
            } else {
                P1[(28*p + nn)*PST + wt]      = a + bb;
                P1[(28*p + nn)*PST + 28 + wt] = a - bb;
            }
        }
    };
    // MM1/MM3: acc[i][j] over rows n_i = 2*(ri*4+i)+p, B = P1 half p
    auto mmRow = [&](){
        #pragma unroll
        for (int i = 0; i < 4; i++)
            #pragma unroll
            for (int j = 0; j < 7; j++) acc[i][j] = 0ULL;
        #pragma unroll 4
        for (int k = 0; k < 28; k++){
            const float* brow = &P1[(28*p + k)*PST + tc];
            #pragma unroll
            for (int j = 0; j < 7; j++) bvec[j] = *(const ull*)(brow + 2*j);
            #pragma unroll
            for (int i = 0; i < 4; i++){
                int n = 2*(ri*4 + i) + p;
                ull ad = dup2(CsH[n*29 + k]);
                #pragma unroll
                for (int j = 0; j < 7; j++) fma2(acc[i][j], ad, bvec[j]);
            }
        }
    };
    // MM2/MM4: A = P1 slot rows (folded data), B = CbF
    auto mmCol = [&](){
        #pragma unroll
        for (int i = 0; i < 4; i++)
            #pragma unroll
            for (int j = 0; j < 7; j++) acc[i][j] = 0ULL;
        #pragma unroll 4
        for (int k = 0; k < 28; k++){
            const float* brow = &CbF[k*58 + tc];
            #pragma unroll
            for (int j = 0; j < 7; j++) bvec[j] = *(const ull*)(brow + 2*j);
            #pragma unroll
            for (int i = 0; i < 4; i++){
                int sr = 28*p + ri*4 + i;
                ull ad;
                if (MODE == 0) ad = *(const ull*)&P1[sr*PST + 2*k];
                else           ad = dup2(P1[sr*PST + k + coff]);
                #pragma unroll
                for (int j = 0; j < 7; j++) fma2(acc[i][j], ad, bvec[j]);
            }
        }
    };

    // ---- pipeline ----
    rowfold();                     // pre1
    __syncthreads();
    if (act){                      // MM1 -> P0 (natural rows, own parity)
        mmRow();
        #pragma unroll
        for (int i = 0; i < 4; i++){
            int n = 2*(ri*4 + i) + p;
            #pragma unroll
            for (int j = 0; j < 7; j++) *(ull*)&P0[n*PST + tc + 2*j] = acc[i][j];
        }
    }
    __syncwarp();
    colfold();                     // pre2 (row-local)
    __syncwarp();
    if (act){                      // MM2 (* mult) -> P0
        mmCol();
        int par = (MODE==1) ? tc/28 : 0;
        const float* mp = multT + (size_t)(c + C_*par)*HW_;
        int mc = (MODE==1) ? (28*s + (tc - par*28)) : tc;
        #pragma unroll
        for (int i = 0; i < 4; i++){
            int n = 2*(ri*4 + i) + p;
            #pragma unroll
            for (int j = 0; j < 7; j++){
                ull mv = *(const ull*)&mp[n*56 + mc + 2*j];
                *(ull*)&P0[n*PST + tc + 2*j] = mul2(acc[i][j], mv);
            }
        }
    }
    __syncthreads();
    rowfold();                     // pre3
    __syncthreads();
    if (act){                      // MM3 -> P0
        mmRow();
        #pragma unroll
        for (int i = 0; i < 4; i++){
            int n = 2*(ri*4 + i) + p;
            #pragma unroll
            for (int j = 0; j < 7; j++) *(ull*)&P0[n*PST + tc + 2*j] = acc[i][j];
        }
    }
    __syncwarp();
    colfold();                     // pre4 (row-local)
    __syncwarp();
    if (act){                      // MM4 -> gmem
        mmCol();
        int par = (MODE==1) ? tc/28 : 0;
        float* op = outA + (size_t)(c + C_*par)*M_ + (size_t)b*HW_;
        int oc = (MODE==1) ? (28*s + (tc - par*28)) : tc;
        #pragma unroll
        for (int i = 0; i < 4; i++){
            int n = 2*(ri*4 + i) + p;
            #pragma unroll
            for (int j = 0; j < 7; j++)
                *(ull*)&op[n*56 + oc + 2*j] = acc[i][j];
        }
    }
}

// ----------------------- LayerNorm(y3) * silu(z), cm -----------------------
__global__ __launch_bounds__(256) void lngate_k(const float* __restrict__ gam,
                                                const float* __restrict__ bet)
{
    __shared__ float sy[C_][33];
    __shared__ float smu[32], srs[32];
    int bp0 = blockIdx.x*32;
    int lane = threadIdx.x & 31, w = threadIdx.x >> 5;
    #pragma unroll
    for (int i = w; i < C_; i += 8)
        sy[i][lane] = g_y3[(size_t)i*M_ + bp0 + lane];
    __syncthreads();
    #pragma unroll
    for (int q = 0; q < 4; q++){
        int p = w*4 + q;
        float sum = 0.f;
        #pragma unroll
        for (int k = 0; k < 6; k++) sum += sy[lane + 32*k][p];
        #pragma unroll
        for (int o = 16; o > 0; o >>= 1) sum += __shfl_xor_sync(0xffffffffu, sum, o);
        float mu = sum * (1.0f/C_);
        float qv = 0.f;
        #pragma unroll
        for (int k = 0; k < 6; k++){ float d = sy[lane + 32*k][p] - mu; qv += d*d; }
        #pragma unroll
        for (int o = 16; o > 0; o >>= 1) qv += __shfl_xor_sync(0xffffffffu, qv, o);
        if (lane == 0){ smu[p] = mu; srs[p] = rsqrtf(qv*(1.0f/C_) + 1e-5f); }
    }
    __syncthreads();
    #pragma unroll
    for (int i = w; i < C_; i += 8){
        float g = gam[i], bb = bet[i];
        float zz = g_t1[(size_t)(C_ + i)*M_ + bp0 + lane];
        float sil = zz / (1.0f + expf(-zz));
        g_yg[(size_t)i*M_ + bp0 + lane] =
            ((sy[i][lane] - smu[lane])*srs[lane]*g + bb) * sil;
    }
}

// --------------------------------- launch ----------------------------------
extern "C" void kernel_launch(void* const* d_in, const int* in_sizes, int n_in,
                              void* d_out, int out_size)
{
    const float* x        = (const float*)d_in[0];
    const float* fe       = (const float*)d_in[1];
    const float* ot       = (const float*)d_in[2];
    const float* dw_w     = (const float*)d_in[3];
    const float* dw_b     = (const float*)d_in[4];
    const float* lin_w    = (const float*)d_in[5];
    const float* lin_b    = (const float*)d_in[6];
    const float* tok_w    = (const float*)d_in[7];
    const float* tok_b    = (const float*)d_in[8];
    const float* lin2_w   = (const float*)d_in[9];
    const float* lin2_b   = (const float*)d_in[10];
    const float* tok2_w   = (const float*)d_in[11];
    const float* tok2_b   = (const float*)d_in[12];
    const float* lin3_w   = (const float*)d_in[13];
    const float* lin3_b   = (const float*)d_in[14];
    const float* norm_g   = (const float*)d_in[15];
    const float* norm_b   = (const float*)d_in[16];
    const float* out_w    = (const float*)d_in[17];
    const float* out_b    = (const float*)d_in[18];
    float* out = (float*)d_out;

    float *y0, *t1, *xc, *otT, *xd, *y3, *yg;
    float *femixT, *mult1T, *xmeanT, *skftT, *mult2T;
    float *cosT, *cosP;
    cudaGetSymbolAddress((void**)&y0,     g_y0);
    cudaGetSymbolAddress((void**)&t1,     g_t1);
    cudaGetSymbolAddress((void**)&xc,     g_xc);
    cudaGetSymbolAddress((void**)&otT,    g_otT);
    cudaGetSymbolAddress((void**)&xd,     g_xd);
    cudaGetSymbolAddress((void**)&y3,     g_y3);
    cudaGetSymbolAddress((void**)&yg,     g_yg);
    cudaGetSymbolAddress((void**)&femixT, g_femixT);
    cudaGetSymbolAddress((void**)&mult1T, g_mult1T);
    cudaGetSymbolAddress((void**)&xmeanT, g_xmeanT);
    cudaGetSymbolAddress((void**)&skftT,  g_skftT);
    cudaGetSymbolAddress((void**)&mult2T, g_mult2T);
    cudaGetSymbolAddress((void**)&cosT,   g_cosT);
    cudaGetSymbolAddress((void**)&cosP,   g_cosP);

    // smem: CsH 56*29 + CbF 28*58 + 2 planes * 2 buffers * 56*PST
    const int DCT_SMEM = (56*29 + 28*58 + 2*2*56*PST) * 4;   // 64960 B
    cudaFuncSetAttribute(dct_k<0>, cudaFuncAttributeMaxDynamicSharedMemorySize, DCT_SMEM);
    cudaFuncSetAttribute(dct_k<1>, cudaFuncAttributeMaxDynamicSharedMemorySize, DCT_SMEM);

    init_k<<<(HW_+255)/256, 256>>>();
    dwconv_k<<<B_*C_, 256>>>(x, dw_w, dw_b);
    transp_k<<<dim3(C_/32, M_/32), 256>>>(ot);
    otfemix_k<<<(HW_*C_/4 + 255)/256, 256>>>(fe);

    cmgemm_k<1><<<dim3(HW_/64, C_/64), 256>>>(tok_w, femixT, tok_b, mult1T,
                                              C_, HW_, C_);
    tgemm_k<0><<<dim3(C2_/192, M_/128), 256>>>(y0, lin_w, lin_b, t1, C_);
    dct_k<0><<<B_*C_/2, 128, DCT_SMEM>>>(t1, nullptr, xc, mult1T, cosT);

    xmean_k<<<(HW_*C2_/4 + 255)/256, 256>>>();
    cmgemm_k<0><<<dim3(HW_/64, C2_/64), 256>>>(lin2_w, xmeanT, lin2_b, skftT,
                                               C2_, HW_, C2_);
    cmgemm_k<1><<<dim3(HW_/64, C2_/64), 256>>>(tok2_w, skftT, tok2_b, mult2T,
                                               C2_, HW_, C2_);
    dct_k<1><<<B_*C2_/2, 128, DCT_SMEM>>>(xc, otT, xd, mult2T, cosP);

    tgemm_k<0><<<dim3(1, M_/128), 256>>>(xd, lin3_w, lin3_b, y3, C2_);
    lngate_k<<<M_/32, 256>>>(norm_g, norm_b);
    tgemm_k<1><<<dim3(1, M_/128), 256>>>(yg, out_w, out_b, out, C_);
}